// round 8
// baseline (speedup 1.0000x reference)
#include <cuda_runtime.h>
#include <cuda_bf16.h>

#define NN 8192
#define ECAP (1u << 23)   // 8M edge slots (32MB static) — ~100x over ~78k expected

// Static scratch (no allocation anywhere). All counters reset by hc_finish.
__device__ unsigned int d_necnt;        // emitted strictly-upper positives == U (exact)
__device__ unsigned int d_dcount;       // diagonal positives
__device__ unsigned int d_edges[ECAP];  // compacted edge list: (row<<13)|col

// Upper-triangle scan, block per row pair (row, NN-1-row): NN+1 elements per
// block -> perfect balance. Hot loop: 4 batched LDG.128 (uniform trip count,
// predicated), popcount-style k, ONE uniform warp branch via ballot. Edges
// are emitted to a compacted global buffer (single atomicAdd on the rare
// path, ~70k total) — no per-element counting chain remains in the loop.
// Exactness: adj is bitwise symmetric -> full positives = 2U + D, and the
// reference's sum(adj>0)//2 = U + D//2 exactly. U == d_necnt by emission.
__global__ void __launch_bounds__(256) hc_scan(const float* __restrict__ adj) {
    const int t = threadIdx.x;
    const int pair = blockIdx.x;

    #pragma unroll
    for (int half = 0; half < 2; half++) {
        const int row = half ? (NN - 1 - pair) : pair;
        const float4* __restrict__ rowp = (const float4*)(adj + (size_t)row * NN);
        const int start4 = row >> 2;            // quad containing the diagonal
        const unsigned enc_row = (unsigned)row << 13;

        if (t == 0) {
            // diagonal quad: cols may be <, ==, or > row
            float4 v = rowp[start4];
            int col0 = start4 << 2;
            float e[4] = {v.x, v.y, v.z, v.w};
            unsigned dd = 0;
            #pragma unroll
            for (int j = 0; j < 4; j++) {
                int col = col0 + j;
                if (e[j] > 0.0f) {
                    if (col == row) dd++;
                    else if (col > row) {
                        unsigned b = atomicAdd(&d_necnt, 1u);
                        if (b < ECAP) d_edges[b] = enc_row | (unsigned)col;
                    }
                }
            }
            if (dd) atomicAdd(&d_dcount, dd);
        }

        const int lim = NN / 4;
        for (int ib = start4 + 1; ib < lim; ib += 1024) {
            const float4 NEG = make_float4(-1.f, -1.f, -1.f, -1.f);
            const int i0 = ib + t;
            float4 v0 = NEG, v1 = NEG, v2 = NEG, v3 = NEG;
            if (i0       < lim) v0 = rowp[i0];
            if (i0 + 256 < lim) v1 = rowp[i0 + 256];
            if (i0 + 512 < lim) v2 = rowp[i0 + 512];
            if (i0 + 768 < lim) v3 = rowp[i0 + 768];

            unsigned k = (unsigned)(v0.x > 0.f) + (unsigned)(v0.y > 0.f)
                       + (unsigned)(v0.z > 0.f) + (unsigned)(v0.w > 0.f)
                       + (unsigned)(v1.x > 0.f) + (unsigned)(v1.y > 0.f)
                       + (unsigned)(v1.z > 0.f) + (unsigned)(v1.w > 0.f)
                       + (unsigned)(v2.x > 0.f) + (unsigned)(v2.y > 0.f)
                       + (unsigned)(v2.z > 0.f) + (unsigned)(v2.w > 0.f)
                       + (unsigned)(v3.x > 0.f) + (unsigned)(v3.y > 0.f)
                       + (unsigned)(v3.z > 0.f) + (unsigned)(v3.w > 0.f);

            // uniform warp branch: whole warp skips when no lane has a hit
            if (__ballot_sync(0xFFFFFFFFu, k != 0u)) {
                if (k) {
                    unsigned idx = atomicAdd(&d_necnt, k);
                    #pragma unroll
                    for (int q = 0; q < 4; q++) {
                        float4 v = (q == 0) ? v0 : (q == 1) ? v1 : (q == 2) ? v2 : v3;
                        int col0 = (i0 + q * 256) << 2;
                        float e[4] = {v.x, v.y, v.z, v.w};
                        #pragma unroll
                        for (int j = 0; j < 4; j++) {
                            if (e[j] > 0.f) {
                                if (idx < ECAP)
                                    d_edges[idx] = enc_row | (unsigned)(col0 + j);
                                idx++;
                            }
                        }
                    }
                }
            }
        }
    }
}

// Single block: Shiloach-Vishkin min-label propagation in shared memory.
// Edge pass: coalesced reads of the compacted list (high MLP, L2-resident),
// atomicMin into spread smem addresses (no hot-root contention). Then 2
// pointer-jump compress rounds. Repeat until an edge pass sees no change
// (~diameter/2 iterations, ~4 for this graph). At fixpoint labels are
// constant per component; lab[i]==i exactly at each component's min node.
__global__ void __launch_bounds__(1024) hc_finish(float* __restrict__ out) {
    __shared__ int lab[NN];                  // 32KB
    __shared__ int sh[1024];
    __shared__ int s_changed;
    const int t = threadIdx.x;

    #pragma unroll
    for (int k = 0; k < NN / 1024; k++)
        lab[t + k * 1024] = t + k * 1024;
    __syncthreads();

    const unsigned n = min(d_necnt, ECAP);

    for (int iter = 0; iter < 64; iter++) {
        if (t == 0) s_changed = 0;
        __syncthreads();

        // hook: propagate smaller label across each edge
        for (unsigned i = t; i < n; i += 1024) {
            unsigned e = d_edges[i];
            int u = (int)(e >> 13), v = (int)(e & 8191u);
            int lu = lab[u], lv = lab[v];
            if (lu < lv) {
                if (atomicMin(&lab[v], lu) > lu) s_changed = 1;
            } else if (lv < lu) {
                if (atomicMin(&lab[u], lv) > lv) s_changed = 1;
            }
        }
        __syncthreads();
        if (!s_changed) break;

        // compress: 2 pointer-jump rounds (benign races; labels only shrink
        // and always remain indices within the same component)
        #pragma unroll
        for (int r = 0; r < 2; r++) {
            #pragma unroll
            for (int k = 0; k < NN / 1024; k++) {
                int i = t + k * 1024;
                lab[i] = lab[lab[i]];
            }
            __syncthreads();
        }
    }
    __syncthreads();

    int roots = 0;
    #pragma unroll
    for (int k = 0; k < NN / 1024; k++) {
        int i = t + k * 1024;
        roots += (lab[i] == i) ? 1 : 0;
    }
    sh[t] = roots;
    __syncthreads();
    for (int s = 512; s > 0; s >>= 1) {
        if (t < s) sh[t] += sh[t + s];
        __syncthreads();
    }
    if (t == 0) {
        float n_comp  = (float)sh[0];
        unsigned half_edges = d_necnt + (d_dcount >> 1);   // (2U+D)//2
        float n_edges = (float)half_edges;
        float betti1  = n_edges - (float)NN + n_comp;
        float n_cyc   = fmaxf(0.0f, betti1);
        float comp_l  = (n_comp - 1.0f) * (n_comp - 1.0f);
        out[0] = comp_l + n_cyc * n_cyc;
        // reset accumulators for the next replay
        d_necnt = 0u; d_dcount = 0u;
    }
}

extern "C" void kernel_launch(void* const* d_in, const int* in_sizes, int n_in,
                              void* d_out, int out_size) {
    const float* adj = (const float*)d_in[0];
    float* out = (float*)d_out;

    hc_scan<<<NN / 2, 256>>>(adj);
    hc_finish<<<1, 1024>>>(out);
}

// round 9
// speedup vs baseline: 1.7920x; 1.7920x over previous
#include <cuda_runtime.h>
#include <cuda_bf16.h>

#define NN 8192
#define ECAP (1u << 20)    // 1M compacted edge slots (4MB) — ~13x over ~78k
#define BUFCAP 4096u       // per-block smem staging (16KB)
#define OVF_CAP (1u << 18) // spill safety

// Static scratch. All counters reset by hc_finish each run.
__device__ unsigned int d_necnt;        // compacted edges == strictly-upper positives
__device__ unsigned int d_dcount;       // diagonal positives
__device__ unsigned int d_edges[ECAP];  // (row<<13)|col
__device__ unsigned int d_ovfcnt;
__device__ unsigned int d_ovf[OVF_CAP];

// Upper-triangle scan, block per row pair (row, NN-1-row): NN+1 elements per
// block -> perfect balance. Hot loop (R6-proven ~4.3 TB/s): 4 batched
// LDG.128, straight-line count, one uniform warp branch via ballot; hits
// append to a SMEM staging buffer (smem atomics only). Block end: ONE global
// atomicAdd reserves a range in the compacted list + coalesced copy-out.
// Exactness: adj bitwise symmetric -> full positives = 2U + D; the
// reference's sum(adj>0)//2 = U + D//2 exactly.
__global__ void __launch_bounds__(256) hc_scan(const float* __restrict__ adj) {
    __shared__ unsigned s_cnt;
    __shared__ unsigned s_base;
    __shared__ unsigned s_buf[BUFCAP];
    const int t = threadIdx.x;
    const int pair = blockIdx.x;
    if (t == 0) s_cnt = 0u;
    __syncthreads();

    #pragma unroll
    for (int half = 0; half < 2; half++) {
        const int row = half ? (NN - 1 - pair) : pair;
        const float4* __restrict__ rowp = (const float4*)(adj + (size_t)row * NN);
        const int start4 = row >> 2;            // quad containing the diagonal
        const unsigned enc_row = (unsigned)row << 13;

        if (t == 0) {
            // diagonal quad: cols may be <, ==, or > row
            float4 v = rowp[start4];
            int col0 = start4 << 2;
            float e[4] = {v.x, v.y, v.z, v.w};
            unsigned dd = 0;
            #pragma unroll
            for (int j = 0; j < 4; j++) {
                int col = col0 + j;
                if (e[j] > 0.0f) {
                    if (col == row) dd++;
                    else if (col > row) {
                        unsigned b = atomicAdd(&s_cnt, 1u);
                        if (b < BUFCAP) s_buf[b] = enc_row | (unsigned)col;
                        else {
                            unsigned o = atomicAdd(&d_ovfcnt, 1u);
                            if (o < OVF_CAP) d_ovf[o] = enc_row | (unsigned)col;
                        }
                    }
                }
            }
            if (dd) atomicAdd(&d_dcount, dd);
        }

        const int lim = NN / 4;
        for (int ib = start4 + 1; ib < lim; ib += 1024) {
            const float4 NEG = make_float4(-1.f, -1.f, -1.f, -1.f);
            const int i0 = ib + t;
            float4 v0 = NEG, v1 = NEG, v2 = NEG, v3 = NEG;
            if (i0       < lim) v0 = rowp[i0];
            if (i0 + 256 < lim) v1 = rowp[i0 + 256];
            if (i0 + 512 < lim) v2 = rowp[i0 + 512];
            if (i0 + 768 < lim) v3 = rowp[i0 + 768];

            unsigned k = (unsigned)(v0.x > 0.f) + (unsigned)(v0.y > 0.f)
                       + (unsigned)(v0.z > 0.f) + (unsigned)(v0.w > 0.f)
                       + (unsigned)(v1.x > 0.f) + (unsigned)(v1.y > 0.f)
                       + (unsigned)(v1.z > 0.f) + (unsigned)(v1.w > 0.f)
                       + (unsigned)(v2.x > 0.f) + (unsigned)(v2.y > 0.f)
                       + (unsigned)(v2.z > 0.f) + (unsigned)(v2.w > 0.f)
                       + (unsigned)(v3.x > 0.f) + (unsigned)(v3.y > 0.f)
                       + (unsigned)(v3.z > 0.f) + (unsigned)(v3.w > 0.f);

            if (__ballot_sync(0xFFFFFFFFu, k != 0u)) {
                if (k) {
                    unsigned idx = atomicAdd(&s_cnt, k);
                    #pragma unroll
                    for (int q = 0; q < 4; q++) {
                        float4 v = (q == 0) ? v0 : (q == 1) ? v1 : (q == 2) ? v2 : v3;
                        int col0 = (i0 + q * 256) << 2;
                        float e[4] = {v.x, v.y, v.z, v.w};
                        #pragma unroll
                        for (int j = 0; j < 4; j++) {
                            if (e[j] > 0.f) {
                                if (idx < BUFCAP)
                                    s_buf[idx] = enc_row | (unsigned)(col0 + j);
                                else {
                                    unsigned o = atomicAdd(&d_ovfcnt, 1u);
                                    if (o < OVF_CAP) d_ovf[o] = enc_row | (unsigned)(col0 + j);
                                }
                                idx++;
                            }
                        }
                    }
                }
            }
        }
    }

    // compact: one global atomic per block, then coalesced copy-out
    __syncthreads();
    if (t == 0) {
        unsigned c = min(s_cnt, BUFCAP);
        s_base = atomicAdd(&d_necnt, c);
    }
    __syncthreads();
    unsigned c = min(s_cnt, BUFCAP);
    unsigned base = s_base;
    for (unsigned i = t; i < c; i += 256)
        if (base + i < ECAP) d_edges[base + i] = s_buf[i];
}

// Single block: Shiloach-Vishkin min-label propagation in smem. Edge pass
// loads uint4 (4 edges/LDG, independent) -> 8 independent LDS -> atomics:
// ~300cyc dependent chain per 4-edge group instead of per edge. Compress =
// 2 pointer-jump rounds. Loop until a pass sees no change (~4 passes).
__device__ __forceinline__ void sv_edge(int* lab, int* changed, unsigned e) {
    int u = (int)(e >> 13), v = (int)(e & 8191u);
    int lu = lab[u], lv = lab[v];
    if (lu < lv)      { if (atomicMin(&lab[v], lu) > lu) *changed = 1; }
    else if (lv < lu) { if (atomicMin(&lab[u], lv) > lv) *changed = 1; }
}

__global__ void __launch_bounds__(1024) hc_finish(float* __restrict__ out) {
    __shared__ int lab[NN];                  // 32KB
    __shared__ int sh[1024];
    __shared__ int s_changed;
    const int t = threadIdx.x;

    #pragma unroll
    for (int k = 0; k < NN / 1024; k++)
        lab[t + k * 1024] = t + k * 1024;
    __syncthreads();

    const unsigned n = min(d_necnt, ECAP);
    const unsigned novf = min(d_ovfcnt, OVF_CAP);
    const unsigned n4 = n >> 2;

    for (int iter = 0; iter < 64; iter++) {
        if (t == 0) s_changed = 0;
        __syncthreads();

        const uint4* e4p = (const uint4*)d_edges;
        for (unsigned i = t; i < n4; i += 1024) {
            uint4 e4 = e4p[i];
            sv_edge(lab, &s_changed, e4.x);
            sv_edge(lab, &s_changed, e4.y);
            sv_edge(lab, &s_changed, e4.z);
            sv_edge(lab, &s_changed, e4.w);
        }
        // tail + overflow (tiny)
        for (unsigned i = (n4 << 2) + t; i < n; i += 1024)
            sv_edge(lab, &s_changed, d_edges[i]);
        for (unsigned i = t; i < novf; i += 1024)
            sv_edge(lab, &s_changed, d_ovf[i]);
        __syncthreads();
        if (!s_changed) break;

        // compress: 2 pointer-jump rounds (benign races; labels only shrink)
        #pragma unroll
        for (int r = 0; r < 2; r++) {
            #pragma unroll
            for (int k = 0; k < NN / 1024; k++) {
                int i = t + k * 1024;
                lab[i] = lab[lab[i]];
            }
            __syncthreads();
        }
    }
    __syncthreads();

    int roots = 0;
    #pragma unroll
    for (int k = 0; k < NN / 1024; k++) {
        int i = t + k * 1024;
        roots += (lab[i] == i) ? 1 : 0;
    }
    sh[t] = roots;
    __syncthreads();
    for (int s = 512; s > 0; s >>= 1) {
        if (t < s) sh[t] += sh[t + s];
        __syncthreads();
    }
    if (t == 0) {
        float n_comp  = (float)sh[0];
        unsigned U = d_necnt + d_ovfcnt;                // exact upper positives
        unsigned half_edges = U + (d_dcount >> 1);      // (2U+D)//2
        float n_edges = (float)half_edges;
        float betti1  = n_edges - (float)NN + n_comp;
        float n_cyc   = fmaxf(0.0f, betti1);
        float comp_l  = (n_comp - 1.0f) * (n_comp - 1.0f);
        out[0] = comp_l + n_cyc * n_cyc;
        // reset for next replay
        d_necnt = 0u; d_dcount = 0u; d_ovfcnt = 0u;
    }
}

extern "C" void kernel_launch(void* const* d_in, const int* in_sizes, int n_in,
                              void* d_out, int out_size) {
    const float* adj = (const float*)d_in[0];
    float* out = (float*)d_out;

    hc_scan<<<NN / 2, 256>>>(adj);
    hc_finish<<<1, 1024>>>(out);
}